// round 14
// baseline (speedup 1.0000x reference)
#include <cuda_runtime.h>
#include <cstdint>

// Per-row mode of x[N, 64], values exactly {0..7}.
//
// R12: R10's full-line load mapping + cheaper reduction.
// Loads (unchanged): thread (r=lane>>3, c=lane&7) owns rows base+r and
// base+r+4; each warp LDG.128 covers 4 COMPLETE 128B lines.
// Reduction (new): one select-exchange at mask 4 moves row(r)'s partials to
// lanes 0-3 of each 8-lane group and row(r+4)'s to lanes 4-7; then a 2-level
// butterfly (masks 1,2) on just 2 regs. Lanes 0 and 4 of each group then run
// ONE SIMD argmax each in parallel (vs two serial in R10).
// Binning: FFMA magic (v*4 + 2^23 -> low bits = 4*bin, exact) +
// funnelshift-wrap + IADD into 8x4-bit nibble fields (max 8 <= 15/field);
// byte-split to even/odd-bin counters (8-lane reduced max 64 < 256).
// Tie-break: smallest bin achieving max count (matches torch.mode).

static constexpr int K = 64;

__device__ __forceinline__ unsigned bin8(float4 u, float4 w)
{
    const float MAGIC = 8388608.0f;  // 2^23; bits = 0x4B000000 | 4*bin
    unsigned n = 0;
    n += __funnelshift_l(0u, 1u, __float_as_uint(fmaf(u.x, 4.0f, MAGIC)));
    n += __funnelshift_l(0u, 1u, __float_as_uint(fmaf(u.y, 4.0f, MAGIC)));
    n += __funnelshift_l(0u, 1u, __float_as_uint(fmaf(u.z, 4.0f, MAGIC)));
    n += __funnelshift_l(0u, 1u, __float_as_uint(fmaf(u.w, 4.0f, MAGIC)));
    n += __funnelshift_l(0u, 1u, __float_as_uint(fmaf(w.x, 4.0f, MAGIC)));
    n += __funnelshift_l(0u, 1u, __float_as_uint(fmaf(w.y, 4.0f, MAGIC)));
    n += __funnelshift_l(0u, 1u, __float_as_uint(fmaf(w.z, 4.0f, MAGIC)));
    n += __funnelshift_l(0u, 1u, __float_as_uint(fmaf(w.w, 4.0f, MAGIC)));
    return n;  // 8x 4-bit fields, max 8
}

__global__ __launch_bounds__(256) void mode_rows_kernel(
    const float4* __restrict__ x4, float* __restrict__ out, int nrows)
{
    const int warp_id = (blockIdx.x * blockDim.x + threadIdx.x) >> 5;
    const int lane    = threadIdx.x & 31;
    const int r       = lane >> 3;   // row slot within first group of 4
    const int c       = lane & 7;    // float4 column (0..7)

    const int base = warp_id * 8;
    if (base >= nrows) return;

    // Rows are 16 float4s. Thread owns rows base+r and base+r+4.
    const float4* p0 = x4 + ((size_t)(base + r)     << 4) + c;
    const float4* p1 = x4 + ((size_t)(base + r + 4) << 4) + c;
    const float4 u0 = p0[0];   // row r,   line 0
    const float4 u1 = p0[8];   // row r,   line 1
    const float4 w0 = p1[0];   // row r+4, line 0
    const float4 w1 = p1[8];   // row r+4, line 1

    const unsigned n0 = bin8(u0, u1);   // nibble histogram, row base+r
    const unsigned n1 = bin8(w0, w1);   // nibble histogram, row base+r+4

    // Nibble -> byte fields. A: bins {0,2,4,6}, B: bins {1,3,5,7}.
    const unsigned A0 = n0 & 0x0F0F0F0Fu, B0 = (n0 >> 4) & 0x0F0F0F0Fu;
    const unsigned A1 = n1 & 0x0F0F0F0Fu, B1 = (n1 >> 4) & 0x0F0F0F0Fu;

    // Select-exchange at mask 4: lanes 0-3 of each 8-lane group accumulate
    // row base+r's histogram; lanes 4-7 accumulate row base+r+4's.
    const bool hi = (lane & 4) != 0;
    unsigned X = (hi ? A1 : A0) + __shfl_xor_sync(0xFFFFFFFFu, hi ? A0 : A1, 4);
    unsigned Y = (hi ? B1 : B0) + __shfl_xor_sync(0xFFFFFFFFu, hi ? B0 : B1, 4);

    // 2-level butterfly within 4-lane subgroups (masks 1,2).
    #pragma unroll
    for (int m = 1; m <= 2; m <<= 1) {
        X += __shfl_xor_sync(0xFFFFFFFFu, X, m);
        Y += __shfl_xor_sync(0xFFFFFFFFu, Y, m);
    }

    // Lanes 0,4,8,...,28 each hold one complete 8-bin histogram.
    if ((lane & 3) == 0) {
        // X: byte counts of bins {0,2,4,6}; Y: bins {1,3,5,7}.
        unsigned m = __vmaxu4(X, Y);
        m = __vmaxu4(m, m >> 16);
        m = __vmaxu4(m, m >> 8);
        const unsigned bc = (m & 0xFFu) * 0x01010101u;
        const int pA = __ffs(__vcmpeq4(X, bc));     // lowest matching even bin
        const int pB = __ffs(__vcmpeq4(Y, bc));     // lowest matching odd bin
        const int binA = pA ? (((pA - 1) >> 3) << 1)       : 8;
        const int binB = pB ? ((((pB - 1) >> 3) << 1) | 1) : 8;
        out[base + r + (lane & 4)] = (float)min(binA, binB);
    }
}

extern "C" void kernel_launch(void* const* d_in, const int* in_sizes, int n_in,
                              void* d_out, int out_size)
{
    const float4* x4 = (const float4*)d_in[0];
    float* out       = (float*)d_out;
    const int nrows  = in_sizes[0] / K;               // 1048576

    const int warps_needed = (nrows + 7) / 8;         // 8 rows per warp
    const int blocks       = (warps_needed + 7) / 8;  // 8 warps per block
    mode_rows_kernel<<<blocks, 256>>>(x4, out, nrows);
}

// round 15
// speedup vs baseline: 1.0502x; 1.0502x over previous
#include <cuda_runtime.h>
#include <cstdint>

// Per-row mode of x[N, 64], values exactly {0..7}.
//
// R14: 16 rows/warp (4KB), 8 front-batched streaming LDG.128 per thread.
//  - Group g = lane>>3 owns rows base+g+4i, i=0..3; lane c = lane&7 reads
//    float4s c and c+8 of each owned row -> every warp load instruction
//    covers 4 COMPLETE 128B lines (full-line pattern kept from R10/R12).
//  - __ldcs (evict-first streaming): zero-reuse stream, skip normal
//    cache allocation priority in L1/L2.
//  - FFMA magic binning (v*4 + 2^23 -> low bits = 4*bin, exact) +
//    funnelshift-wrap + IADD into 8x4-bit nibble fields (max 8/field).
//  - Reduction tree: mask-4 select-exchange (rows {0,1} to lo half,
//    {2,3} to hi half), mask-2 select-exchange (one row per lane pair),
//    mask-1 butterfly. Byte fields max 64 < 256: carry-free.
//  - 16 lanes run SIMD argmax in parallel, one row each; ascending
//    tie-break (smallest bin at max count) matches torch.mode.

static constexpr int K = 64;

__device__ __forceinline__ unsigned bin8(float4 u, float4 w)
{
    const float MAGIC = 8388608.0f;  // 2^23; bits = 0x4B000000 | 4*bin
    unsigned n = 0;
    n += __funnelshift_l(0u, 1u, __float_as_uint(fmaf(u.x, 4.0f, MAGIC)));
    n += __funnelshift_l(0u, 1u, __float_as_uint(fmaf(u.y, 4.0f, MAGIC)));
    n += __funnelshift_l(0u, 1u, __float_as_uint(fmaf(u.z, 4.0f, MAGIC)));
    n += __funnelshift_l(0u, 1u, __float_as_uint(fmaf(u.w, 4.0f, MAGIC)));
    n += __funnelshift_l(0u, 1u, __float_as_uint(fmaf(w.x, 4.0f, MAGIC)));
    n += __funnelshift_l(0u, 1u, __float_as_uint(fmaf(w.y, 4.0f, MAGIC)));
    n += __funnelshift_l(0u, 1u, __float_as_uint(fmaf(w.z, 4.0f, MAGIC)));
    n += __funnelshift_l(0u, 1u, __float_as_uint(fmaf(w.w, 4.0f, MAGIC)));
    return n;  // 8x 4-bit fields, max 8
}

__global__ __launch_bounds__(256) void mode_rows_kernel(
    const float4* __restrict__ x4, float* __restrict__ out, int nrows)
{
    const int warp_id = (blockIdx.x * blockDim.x + threadIdx.x) >> 5;
    const int lane    = threadIdx.x & 31;
    const int g       = lane >> 3;   // 8-lane group: owns rows base+g+4i
    const int c       = lane & 7;    // float4 column (0..7)

    const int base = warp_id * 16;
    if (base >= nrows) return;

    // Row = 16 float4s; owned rows are 4 rows (64 float4) apart.
    const float4* p = x4 + (((size_t)(base + g)) << 4) + c;

    // 8 independent streaming loads, front-batched for max MLP.
    const float4 u0 = __ldcs(p);            const float4 w0 = __ldcs(p + 8);
    const float4 u1 = __ldcs(p + 64);       const float4 w1 = __ldcs(p + 72);
    const float4 u2 = __ldcs(p + 128);      const float4 w2 = __ldcs(p + 136);
    const float4 u3 = __ldcs(p + 192);      const float4 w3 = __ldcs(p + 200);

    const unsigned n0 = bin8(u0, w0);   // row base+g
    const unsigned n1 = bin8(u1, w1);   // row base+g+4
    const unsigned n2 = bin8(u2, w2);   // row base+g+8
    const unsigned n3 = bin8(u3, w3);   // row base+g+12

    // Nibble -> byte fields. A: bins {0,2,4,6}, B: bins {1,3,5,7}.
    const unsigned A0 = n0 & 0x0F0F0F0Fu, B0 = (n0 >> 4) & 0x0F0F0F0Fu;
    const unsigned A1 = n1 & 0x0F0F0F0Fu, B1 = (n1 >> 4) & 0x0F0F0F0Fu;
    const unsigned A2 = n2 & 0x0F0F0F0Fu, B2 = (n2 >> 4) & 0x0F0F0F0Fu;
    const unsigned A3 = n3 & 0x0F0F0F0Fu, B3 = (n3 >> 4) & 0x0F0F0F0Fu;

    // Mask-4 select-exchange: lo half keeps rows {0,1}, hi half rows {2,3}.
    const bool hi = (lane & 4) != 0;
    unsigned XA0 = (hi ? A2 : A0) + __shfl_xor_sync(0xFFFFFFFFu, hi ? A0 : A2, 4);
    unsigned XB0 = (hi ? B2 : B0) + __shfl_xor_sync(0xFFFFFFFFu, hi ? B0 : B2, 4);
    unsigned XA1 = (hi ? A3 : A1) + __shfl_xor_sync(0xFFFFFFFFu, hi ? A1 : A3, 4);
    unsigned XB1 = (hi ? B3 : B1) + __shfl_xor_sync(0xFFFFFFFFu, hi ? B1 : B3, 4);

    // Mask-2 select-exchange: each lane pair keeps one row (i = 2*hi + b1).
    const bool b1 = (lane & 2) != 0;
    unsigned X = (b1 ? XA1 : XA0) + __shfl_xor_sync(0xFFFFFFFFu, b1 ? XA0 : XA1, 2);
    unsigned Y = (b1 ? XB1 : XB0) + __shfl_xor_sync(0xFFFFFFFFu, b1 ? XB0 : XB1, 2);

    // Mask-1 butterfly completes the 8-lane sum (field max 64 < 256).
    X += __shfl_xor_sync(0xFFFFFFFFu, X, 1);
    Y += __shfl_xor_sync(0xFFFFFFFFu, Y, 1);

    // Even lanes each hold one complete histogram; 16 rows, 16 writers.
    if ((lane & 1) == 0) {
        unsigned m = __vmaxu4(X, Y);
        m = __vmaxu4(m, m >> 16);
        m = __vmaxu4(m, m >> 8);
        const unsigned bc = (m & 0xFFu) * 0x01010101u;
        const int pA = __ffs(__vcmpeq4(X, bc));     // lowest matching even bin
        const int pB = __ffs(__vcmpeq4(Y, bc));     // lowest matching odd bin
        const int binA = pA ? (((pA - 1) >> 3) << 1)       : 8;
        const int binB = pB ? ((((pB - 1) >> 3) << 1) | 1) : 8;
        // row = base + g + 4*(2*hi + b1) = base + g + ((lane&6)<<1)
        out[base + g + ((lane & 6) << 1)] = (float)min(binA, binB);
    }
}

extern "C" void kernel_launch(void* const* d_in, const int* in_sizes, int n_in,
                              void* d_out, int out_size)
{
    const float4* x4 = (const float4*)d_in[0];
    float* out       = (float*)d_out;
    const int nrows  = in_sizes[0] / K;                // 1048576

    const int warps_needed = (nrows + 15) / 16;        // 16 rows per warp
    const int blocks       = (warps_needed + 7) / 8;   // 8 warps per block
    mode_rows_kernel<<<blocks, 256>>>(x4, out, nrows);
}